// round 1
// baseline (speedup 1.0000x reference)
#include <cuda_runtime.h>

#define NN 50000
#define NE 800000
#define DD 128
#define NC 10
#define NG 64

// ---------------- scratch (static device globals; no runtime alloc) --------
__device__ float g_buf0[NN * DD];   // GEMM output y = dis * (h @ W)
__device__ float g_buf1[NN * DD];   // aggregation output h' (relu)
__device__ float g_dis[NN];
__device__ int   g_deg[NN];
__device__ int   g_off[NN + 1];
__device__ int   g_cur[NN];
__device__ int   g_csr[NE];
__device__ float g_pool[NG * DD];
__device__ float g_cnt[NG];
__device__ int   g_anyodd;          // 0 => indices are int64, nonzero => int32

// index load that works for both int32 and int64 input tensors
__device__ __forceinline__ int ld_idx(const void* p, long long i, int is64) {
    return is64 ? (int)((const long long*)p)[i] : ((const int*)p)[i];
}

// ---------------- setup kernels --------------------------------------------
__global__ void k_zero() {
    int i = blockIdx.x * blockDim.x + threadIdx.x;
    if (i < NN) g_deg[i] = 0;
    if (i == 0) g_anyodd = 0;
}

// If edge_index is int64, every odd 32-bit word is the high half of a value
// < 50000, i.e. zero. If int32, odd words are random node ids (≈never all 0).
__global__ void k_detect(const void* ei) {
    int t = threadIdx.x;
    int any = 0;
    for (int i = t; i < 4096; i += 256)
        any |= ((const int*)ei)[2 * i + 1];
    if (any) atomicOr(&g_anyodd, 1);
}

__global__ void k_deg(const void* ei) {
    int e = blockIdx.x * blockDim.x + threadIdx.x;
    if (e >= NE) return;
    int is64 = (g_anyodd == 0);
    int c = ld_idx(ei, (long long)NE + e, is64);
    atomicAdd(&g_deg[c], 1);
}

__global__ void k_dis() {
    int i = blockIdx.x * blockDim.x + threadIdx.x;
    if (i < NN) g_dis[i] = rsqrtf((float)(g_deg[i] + 1));  // +1 self-loop
}

// single-block exclusive scan of g_deg -> g_off / g_cur
__global__ void k_scan() {
    __shared__ int sm[1024];
    int t = threadIdx.x;
    const int SEG = (NN + 1023) / 1024;  // 49
    int s0 = t * SEG;
    int s1 = min(s0 + SEG, NN);
    int local = 0;
    for (int i = s0; i < s1; i++) local += g_deg[i];
    sm[t] = local;
    __syncthreads();
    for (int off = 1; off < 1024; off <<= 1) {
        int v = (t >= off) ? sm[t - off] : 0;
        __syncthreads();
        sm[t] += v;
        __syncthreads();
    }
    int run = sm[t] - local;  // exclusive prefix
    for (int i = s0; i < s1; i++) {
        g_off[i] = run;
        g_cur[i] = run;
        run += g_deg[i];
    }
    if (t == 1023) g_off[NN] = sm[1023];
}

__global__ void k_scatter(const void* ei) {
    int e = blockIdx.x * blockDim.x + threadIdx.x;
    if (e >= NE) return;
    int is64 = (g_anyodd == 0);
    int r = ld_idx(ei, e, is64);
    int c = ld_idx(ei, (long long)NE + e, is64);
    int pos = atomicAdd(&g_cur[c], 1);
    g_csr[pos] = r;
}

// ---------------- GEMM: Y = dis .* (A @ W), A [NN,128], W [128,128] --------
// layer==0: A = x (external).  layer==1: A = g_buf1.  Output always g_buf0.
#define GM 64
__global__ void __launch_bounds__(256) k_gemm(const float* __restrict__ x_ext,
                                              const float* __restrict__ W,
                                              int layer) {
    __shared__ float Ws[32][DD];      // [k][n], rows 16B-aligned
    __shared__ float As[32][GM + 1];  // [k][m], padded
    const float* __restrict__ A = (layer == 0) ? x_ext : g_buf1;
    float* __restrict__ Y = g_buf0;

    int t = threadIdx.x;
    int m0 = blockIdx.x * GM;
    int tr = t >> 5;   // 0..7  (8 row-groups)
    int tc = t & 31;   // 0..31 (32 col-groups of 4)

    float4 acc[8];
#pragma unroll
    for (int i = 0; i < 8; i++) acc[i] = make_float4(0.f, 0.f, 0.f, 0.f);

    for (int k0 = 0; k0 < DD; k0 += 32) {
        // load A tile [64 rows x 32 k] transposed into As[k][m]
#pragma unroll
        for (int q = 0; q < 2; q++) {
            int id = q * 256 + t;      // 0..511
            int r  = id >> 3;          // 0..63
            int kq = id & 7;           // 0..7 (float4 within row)
            int gm = m0 + r;
            float4 v = make_float4(0.f, 0.f, 0.f, 0.f);
            if (gm < NN) v = *(const float4*)&A[(long long)gm * DD + k0 + kq * 4];
            As[kq * 4 + 0][r] = v.x;
            As[kq * 4 + 1][r] = v.y;
            As[kq * 4 + 2][r] = v.z;
            As[kq * 4 + 3][r] = v.w;
        }
        // load W tile [32 k x 128 n]
#pragma unroll
        for (int q = 0; q < 4; q++) {
            int id = q * 256 + t;      // 0..1023
            int kr = id >> 5;          // 0..31
            int cq = id & 31;          // 0..31
            *(float4*)&Ws[kr][cq * 4] =
                *(const float4*)&W[(long long)(k0 + kr) * DD + cq * 4];
        }
        __syncthreads();

#pragma unroll
        for (int kk = 0; kk < 32; kk++) {
            float4 w = *(const float4*)&Ws[kk][tc * 4];
#pragma unroll
            for (int i = 0; i < 8; i++) {
                float a = As[kk][tr * 8 + i];
                acc[i].x += a * w.x;
                acc[i].y += a * w.y;
                acc[i].z += a * w.z;
                acc[i].w += a * w.w;
            }
        }
        __syncthreads();
    }

#pragma unroll
    for (int i = 0; i < 8; i++) {
        int gm = m0 + tr * 8 + i;
        if (gm < NN) {
            float ds = g_dis[gm];
            float4 o = make_float4(ds * acc[i].x, ds * acc[i].y,
                                   ds * acc[i].z, ds * acc[i].w);
            *(float4*)&Y[(long long)gm * DD + tc * 4] = o;
        }
    }
}

// ---------------- aggregation: h' = relu(dis[c]*(y[c]+sum_in y[r]) + b) ----
// in = g_buf0, out = g_buf1. One warp per node; lane owns 4 floats (float4).
__global__ void __launch_bounds__(256) k_agg(const float* __restrict__ bias) {
    int w = (blockIdx.x * blockDim.x + threadIdx.x) >> 5;
    int lane = threadIdx.x & 31;
    if (w >= NN) return;
    const float4* __restrict__ yv = (const float4*)g_buf0;
    float4 a0 = yv[(long long)w * 32 + lane];  // self-loop contribution y[c]
    float4 a1 = make_float4(0.f, 0.f, 0.f, 0.f);
    int p = g_off[w];
    int e2 = g_off[w + 1];
    for (; p + 1 < e2; p += 2) {
        int r0 = g_csr[p];
        int r1 = g_csr[p + 1];
        float4 v0 = yv[(long long)r0 * 32 + lane];
        float4 v1 = yv[(long long)r1 * 32 + lane];
        a0.x += v0.x; a0.y += v0.y; a0.z += v0.z; a0.w += v0.w;
        a1.x += v1.x; a1.y += v1.y; a1.z += v1.z; a1.w += v1.w;
    }
    if (p < e2) {
        int r0 = g_csr[p];
        float4 v0 = yv[(long long)r0 * 32 + lane];
        a0.x += v0.x; a0.y += v0.y; a0.z += v0.z; a0.w += v0.w;
    }
    float ds = g_dis[w];
    float4 b = ((const float4*)bias)[lane];
    float4 o;
    o.x = fmaxf(ds * (a0.x + a1.x) + b.x, 0.f);
    o.y = fmaxf(ds * (a0.y + a1.y) + b.y, 0.f);
    o.z = fmaxf(ds * (a0.z + a1.z) + b.z, 0.f);
    o.w = fmaxf(ds * (a0.w + a1.w) + b.w, 0.f);
    ((float4*)g_buf1)[(long long)w * 32 + lane] = o;
}

// ---------------- mean pool per graph (batch is sorted; no atomics) --------
__global__ void k_pool(const void* batch) {
    int g = blockIdx.x;
    int is64 = (g_anyodd == 0);
    // lower_bound(batch, g)
    int lo = 0, hi = NN;
    while (lo < hi) {
        int mid = (lo + hi) >> 1;
        if (ld_idx(batch, mid, is64) < g) lo = mid + 1; else hi = mid;
    }
    int start = lo;
    hi = NN;
    while (lo < hi) {
        int mid = (lo + hi) >> 1;
        if (ld_idx(batch, mid, is64) <= g) lo = mid + 1; else hi = mid;
    }
    int end = lo;

    int d = threadIdx.x;  // 128 threads, one dim each
    const float* __restrict__ h = g_buf1;
    float s0 = 0.f, s1 = 0.f, s2 = 0.f, s3 = 0.f;
    int i = start;
    for (; i + 3 < end; i += 4) {
        s0 += h[(long long)i * DD + d];
        s1 += h[(long long)(i + 1) * DD + d];
        s2 += h[(long long)(i + 2) * DD + d];
        s3 += h[(long long)(i + 3) * DD + d];
    }
    for (; i < end; i++) s0 += h[(long long)i * DD + d];
    g_pool[g * DD + d] = (s0 + s1) + (s2 + s3);
    if (d == 0) g_cnt[g] = (float)(end - start);
}

// ---------------- head: emb @ Wfc + bfc, log_softmax -----------------------
__global__ void k_head(const float* __restrict__ Wfc,
                       const float* __restrict__ bfc,
                       float* __restrict__ out) {
    __shared__ float lg[NG][NC];
    int t = threadIdx.x;            // 640 threads
    int g = t / NC, c = t % NC;
    if (t < NG * NC) {
        float inv = 1.f / fmaxf(g_cnt[g], 1.f);
        float acc = bfc[c];
#pragma unroll 4
        for (int d = 0; d < DD; d++)
            acc += g_pool[g * DD + d] * inv * Wfc[d * NC + c];
        lg[g][c] = acc;
    }
    __syncthreads();
    if (t < NG * NC) {
        float m = -1e30f;
#pragma unroll
        for (int k = 0; k < NC; k++) m = fmaxf(m, lg[g][k]);
        float s = 0.f;
#pragma unroll
        for (int k = 0; k < NC; k++) s += expf(lg[g][k] - m);
        out[g * NC + c] = lg[g][c] - m - logf(s);
    }
}

// ---------------- launch ----------------------------------------------------
extern "C" void kernel_launch(void* const* d_in, const int* in_sizes, int n_in,
                              void* d_out, int out_size) {
    (void)in_sizes; (void)n_in; (void)out_size;
    const float* x   = (const float*)d_in[0];
    const void*  ei  = d_in[1];
    const void*  bat = d_in[2];
    const float* W1  = (const float*)d_in[3];
    const float* b1  = (const float*)d_in[4];
    const float* W2  = (const float*)d_in[5];
    const float* b2  = (const float*)d_in[6];
    const float* Wfc = (const float*)d_in[7];
    const float* bfc = (const float*)d_in[8];
    float* out = (float*)d_out;

    k_zero<<<(NN + 255) / 256, 256>>>();
    k_detect<<<1, 256>>>(ei);
    k_deg<<<(NE + 255) / 256, 256>>>(ei);
    k_dis<<<(NN + 255) / 256, 256>>>();
    k_scan<<<1, 1024>>>();
    k_scatter<<<(NE + 255) / 256, 256>>>(ei);

    k_gemm<<<(NN + GM - 1) / GM, 256>>>(x, W1, 0);      // y1 -> buf0
    k_agg<<<(NN * 32 + 255) / 256, 256>>>(b1);          // h1 -> buf1
    k_gemm<<<(NN + GM - 1) / GM, 256>>>(x, W2, 1);      // y2 -> buf0 (A=buf1)
    k_agg<<<(NN * 32 + 255) / 256, 256>>>(b2);          // h2 -> buf1

    k_pool<<<NG, DD>>>(bat);
    k_head<<<1, NG * NC>>>(Wfc, bfc, out);
}